// round 8
// baseline (speedup 1.0000x reference)
#include <cuda_runtime.h>
#include <cstdint>

#define B_  4
#define T_  4096
#define TKP 1024
#define DM  1024
#define HD  128
#define SCALE_INV 0.08838834764831845f   // 1/sqrt(128)

// ---------------- static device scratch ----------------
__device__ float  g_xp[B_ * TKP * DM];   // pooled x: tf32-rounded, DM k-interleaved per 8-block
__device__ float  g_Q [B_ * T_  * HD];   // d-dim interleaved [0,4,1,5,2,6,3,7] per 8-block
__device__ float  g_K [B_ * TKP * HD];   // d-dim interleaved
__device__ float  g_V [B_ * TKP * HD];   // TRANSPOSED [b][d][key], key-interleaved per 8-block
__device__ float  g_Wt[3 * DM * HD];     // tf32 weights, layout [which][kblk][n][8 interleaved]
__device__ float  g_cos[T_ * 64];
__device__ float  g_sin[T_ * 64];
__device__ double g_theta[64];

// ---------------- helpers ----------------
__device__ __forceinline__ unsigned f2t(float x) {
    unsigned r; asm("cvt.rna.tf32.f32 %0, %1;" : "=r"(r) : "f"(x)); return r;
}
__device__ __forceinline__ float f2tf(float x) { return __uint_as_float(f2t(x)); }
__device__ __forceinline__ float4 f2tf4(float4 v) {
    return make_float4(f2tf(v.x), f2tf(v.y), f2tf(v.z), f2tf(v.w));
}
__device__ __forceinline__ void mma8(float* d,
                                     float a0, float a1, float a2, float a3,
                                     float b0, float b1) {
    asm volatile("mma.sync.aligned.m16n8k8.row.col.f32.tf32.tf32.f32 "
                 "{%0,%1,%2,%3},{%4,%5,%6,%7},{%8,%9},{%0,%1,%2,%3};"
                 : "+f"(d[0]), "+f"(d[1]), "+f"(d[2]), "+f"(d[3])
                 : "r"(__float_as_uint(a0)), "r"(__float_as_uint(a1)),
                   "r"(__float_as_uint(a2)), "r"(__float_as_uint(a3)),
                   "r"(__float_as_uint(b0)), "r"(__float_as_uint(b1)));
}
__device__ __forceinline__ void cpa16(uint32_t dst, const void* src) {
    asm volatile("cp.async.cg.shared.global [%0], [%1], 16;" :: "r"(dst), "l"(src));
}

// ---------------- RoPE tables ----------------
__global__ void theta_k() {
    int i = threadIdx.x;
    g_theta[i] = exp(((double)(-i) / 64.0) * log(10000.0));
}
__global__ void rope_table_k() {
    int t = blockIdx.x, i = threadIdx.x;
    float thf = (float)g_theta[i];
    float arg = (float)t * thf;          // fp32 product, matching reference
    const double TWO_PI  = 6.283185307179586476925286766559;
    const double INV2PI  = 0.15915494309189533576888376337251;
    double da = (double)arg;
    double k  = rint(da * INV2PI);
    float  r  = (float)(da - k * TWO_PI);
    g_cos[t * 64 + i] = cosf(r);
    g_sin[t * 64 + i] = sinf(r);
}

// ---------------- weights -> tf32, layout [which][kblk][n][8 interleaved] ----------------
__global__ void cvtW_k(const float* __restrict__ Wq, const float* __restrict__ Wk,
                       const float* __restrict__ Wv) {
    int g = blockIdx.x * 256 + threadIdx.x;   // 3*128*128 = 49152 threads
    int n = g & 127;
    int kb = (g >> 7) & 127;
    int which = g >> 14;
    const float* W = (which == 0) ? Wq : (which == 1 ? Wk : Wv);
    float w[8];
#pragma unroll
    for (int j = 0; j < 8; j++) w[j] = f2tf(W[(size_t)(kb * 8 + j) * HD + n]);
    float* dst = g_Wt + (((size_t)which * 128 + kb) * 128 + n) * 8;
    *(float4*)(dst)     = make_float4(w[0], w[4], w[1], w[5]);
    *(float4*)(dst + 4) = make_float4(w[2], w[6], w[3], w[7]);
}

// ---------------- stride-4 mean pool: tf32-round + k-interleave the DM dim ----------------
__global__ void pool_x_k(const float* __restrict__ x) {
    int g  = blockIdx.x * 256 + threadIdx.x;     // B*TKP*128 threads, one 8-block each
    int d8 = g & 127;
    int row = g >> 7;                            // b*1024 + tp
    int b   = row >> 10, tp = row & 1023;
    const float* base = x + ((size_t)b * T_ + 4 * tp) * DM + d8 * 8;
    float v[8] = {0.f, 0.f, 0.f, 0.f, 0.f, 0.f, 0.f, 0.f};
#pragma unroll
    for (int r = 0; r < 4; r++) {
        float4 a = *(const float4*)(base + (size_t)r * DM);
        float4 c = *(const float4*)(base + (size_t)r * DM + 4);
        v[0] += a.x; v[1] += a.y; v[2] += a.z; v[3] += a.w;
        v[4] += c.x; v[5] += c.y; v[6] += c.z; v[7] += c.w;
    }
#pragma unroll
    for (int j = 0; j < 8; j++) v[j] = f2tf(v[j] * 0.25f);
    float* dst = g_xp + (size_t)row * DM + d8 * 8;
    *(float4*)(dst)     = make_float4(v[0], v[4], v[1], v[5]);
    *(float4*)(dst + 4) = make_float4(v[2], v[6], v[3], v[7]);
}

// ---------------- projection GEMM: interleaved A (K/V) and B, cp.async DB ----
#define AST 36
#define ABUF (128 * AST)
#define BBUF 4096                         // 4 kblk x 128 n x 8
__global__ void __launch_bounds__(256, 2) proj_k(const float* __restrict__ x) {
    extern __shared__ __align__(16) float psm[];
    float* As = psm;
    float* Bs = psm + 2 * ABUF;

    int bid = blockIdx.x;
    const float* A; const float* Wm; float* Cm; int m0;
    bool isQ = false, isV = false;
    if (bid < 128)      { A = x;    Wm = g_Wt;                Cm = g_Q; m0 = bid * 128; isQ = true; }
    else if (bid < 160) { A = g_xp; Wm = g_Wt + DM * HD;      Cm = g_K; m0 = (bid - 128) * 128; }
    else                { A = g_xp; Wm = g_Wt + 2 * DM * HD;  Cm = g_V; m0 = (bid - 160) * 128; isV = true; }

    int tid  = threadIdx.x;
    int lane = tid & 31, wid = tid >> 5;
    int gid  = lane >> 2, tig = lane & 3;
    int wm = wid >> 1, wn = wid & 1;

    uint32_t sA = (uint32_t)__cvta_generic_to_shared(As);
    uint32_t sB = (uint32_t)__cvta_generic_to_shared(Bs);
    int ar = tid >> 3, ac = tid & 7;

    auto stage = [&](int kb, int buf) {
#pragma unroll
        for (int it = 0; it < 4; it++) {
            int r = ar + it * 32;
            cpa16(sA + (uint32_t)((buf * ABUF + r * AST + ac * 4) * 4),
                  A + (size_t)(m0 + r) * DM + kb * 32 + ac * 4);
        }
#pragma unroll
        for (int it = 0; it < 4; it++) {
            int idx = it * 256 + tid;     // float4 index, 1024 total
            cpa16(sB + (uint32_t)((buf * BBUF + idx * 4) * 4),
                  Wm + (size_t)kb * 4096 + idx * 4);
        }
        asm volatile("cp.async.commit_group;");
    };

    float C[2][8][4];
#pragma unroll
    for (int mf = 0; mf < 2; mf++)
#pragma unroll
        for (int nf = 0; nf < 8; nf++)
#pragma unroll
            for (int j = 0; j < 4; j++) C[mf][nf][j] = 0.f;

    stage(0, 0);
    stage(1, 1);

    for (int kb = 0; kb < 32; kb++) {
        if (kb < 30) { asm volatile("cp.async.wait_group 1;"); }
        else         { asm volatile("cp.async.wait_group 0;"); }
        __syncthreads();
        const float* Ab = As + (kb & 1) * ABUF;
        const float* Bb = Bs + (kb & 1) * BBUF;
#pragma unroll
        for (int ks = 0; ks < 4; ks++) {
            int k0 = ks * 8;
            float ah[2][4];
            if (isQ) {
                // raw fp32 A: scalar loads + RN cvt
#pragma unroll
                for (int mf = 0; mf < 2; mf++) {
                    int mb = wm * 32 + mf * 16;
                    ah[mf][0] = f2tf(Ab[(mb + gid)     * AST + k0 + tig]);
                    ah[mf][1] = f2tf(Ab[(mb + gid + 8) * AST + k0 + tig]);
                    ah[mf][2] = f2tf(Ab[(mb + gid)     * AST + k0 + tig + 4]);
                    ah[mf][3] = f2tf(Ab[(mb + gid + 8) * AST + k0 + tig + 4]);
                }
            } else {
                // pre-rounded, interleaved A: LDS.64, no cvt
#pragma unroll
                for (int mf = 0; mf < 2; mf++) {
                    int mb = wm * 32 + mf * 16;
                    float2 a0 = *(const float2*)(Ab + (mb + gid)     * AST + k0 + 2 * tig);
                    float2 a1 = *(const float2*)(Ab + (mb + gid + 8) * AST + k0 + 2 * tig);
                    ah[mf][0] = a0.x; ah[mf][1] = a1.x; ah[mf][2] = a0.y; ah[mf][3] = a1.y;
                }
            }
#pragma unroll
            for (int nf = 0; nf < 8; nf++) {
                int nb = wn * 64 + nf * 8 + gid;
                float2 bb = *(const float2*)(Bb + (ks * 128 + nb) * 8 + 2 * tig);
#pragma unroll
                for (int mf = 0; mf < 2; mf++)
                    mma8(C[mf][nf], ah[mf][0], ah[mf][1], ah[mf][2], ah[mf][3], bb.x, bb.y);
            }
        }
        __syncthreads();
        if (kb + 2 < 32) stage(kb + 2, kb & 1);
    }

    if (isV) {
        // V: write transposed [b][d][key], key-interleaved per 8-block, tf32-rounded
#pragma unroll
        for (int mf = 0; mf < 2; mf++) {
            int gr0 = m0 + wm * 32 + mf * 16 + gid;
            int gr1 = gr0 + 8;
            int vb  = gr0 >> 10;
            int ky0 = gr0 & 1023, ky1 = gr1 & 1023;
            int i0 = ky0 & 7, i1 = ky1 & 7;
            int kp0 = (ky0 & ~7) + ((i0 < 4) ? 2 * i0 : 2 * (i0 - 4) + 1);
            int kp1 = (ky1 & ~7) + ((i1 < 4) ? 2 * i1 : 2 * (i1 - 4) + 1);
            float* Vb0 = g_V + (size_t)vb * HD * TKP;
#pragma unroll
            for (int nf = 0; nf < 8; nf++) {
                int col = wn * 64 + nf * 8 + 2 * tig;
                Vb0[(size_t)col * TKP + kp0]       = f2tf(C[mf][nf][0]);
                Vb0[(size_t)(col + 1) * TKP + kp0] = f2tf(C[mf][nf][1]);
                Vb0[(size_t)col * TKP + kp1]       = f2tf(C[mf][nf][2]);
                Vb0[(size_t)(col + 1) * TKP + kp1] = f2tf(C[mf][nf][3]);
            }
        }
    } else {
#pragma unroll
        for (int mf = 0; mf < 2; mf++) {
            int r0 = m0 + wm * 32 + mf * 16 + gid;
#pragma unroll
            for (int nf = 0; nf < 8; nf++) {
                int col = wn * 64 + nf * 8 + 2 * tig;
                *(float2*)(Cm + (size_t)r0 * HD + col)       = make_float2(C[mf][nf][0], C[mf][nf][1]);
                *(float2*)(Cm + (size_t)(r0 + 8) * HD + col) = make_float2(C[mf][nf][2], C[mf][nf][3]);
            }
        }
    }
}

// ---------------- RoPE + tf32-round + d-interleave, in place (Q, K) ----------------
__global__ void ropep_k(int which) {
    float* X   = which ? g_K : g_Q;
    int mask   = which ? (TKP - 1) : (T_ - 1);
    float scl  = which ? 1.f : SCALE_INV;
    int g  = blockIdx.x * 256 + threadIdx.x;
    int b8 = g & 7;
    int row = g >> 3;
    int pos = row & mask;
    const float4* cp = (const float4*)(g_cos + pos * 64 + b8 * 8);
    const float4* sp = (const float4*)(g_sin + pos * 64 + b8 * 8);
    float c[8], s[8], x1[8], x2[8];
    *(float4*)(c)     = cp[0]; *(float4*)(c + 4) = cp[1];
    *(float4*)(s)     = sp[0]; *(float4*)(s + 4) = sp[1];
    float* p = X + (size_t)row * HD + b8 * 8;
    *(float4*)(x1)     = *(float4*)(p);      *(float4*)(x1 + 4) = *(float4*)(p + 4);
    *(float4*)(x2)     = *(float4*)(p + 64); *(float4*)(x2 + 4) = *(float4*)(p + 68);
    float o1[8], o2[8];
#pragma unroll
    for (int j = 0; j < 8; j++) {
        o1[j] = (x1[j] * c[j] - x2[j] * s[j]) * scl;
        o2[j] = (x2[j] * c[j] + x1[j] * s[j]) * scl;
    }
    *(float4*)(p)      = f2tf4(make_float4(o1[0], o1[4], o1[1], o1[5]));
    *(float4*)(p + 4)  = f2tf4(make_float4(o1[2], o1[6], o1[3], o1[7]));
    *(float4*)(p + 64) = f2tf4(make_float4(o2[0], o2[4], o2[1], o2[5]));
    *(float4*)(p + 68) = f2tf4(make_float4(o2[2], o2[6], o2[3], o2[7]));
}

// ---------------- zero output ----------------
__global__ void zero_k(float* __restrict__ out) {
    ((float4*)out)[blockIdx.x * 256 + threadIdx.x] = make_float4(0.f, 0.f, 0.f, 0.f);
}

// ---------------- flash attention: LDS.64 frags everywhere in mma loops ----------
#define QST 136
#define KST 136
#define VST 72
#define PST 68
__global__ void __launch_bounds__(256, 2) attn_k(const float* __restrict__ alpha_p,
                                                 float* __restrict__ Out)
{
    extern __shared__ __align__(16) float sm[];
    float* Qs  = sm;                        // 64 x 136
    float* KVs = Qs + 64 * QST;             // K: 64 x 136 / V: 128 x 72 (9216 floats)
    float* Ps  = KVs + 9216;                // 64 x 68
    float* wmx = Ps + 64 * PST;             // [2][64]
    float* wsp = wmx + 128;
    float* wsx = wsp + 128;

    int tid  = threadIdx.x;
    int lane = tid & 31, wid = tid >> 5;
    int gid  = lane >> 2, tig = lane & 3;
    int rg   = wid >> 1, half = wid & 1;
    int Q0 = blockIdx.x * 64;
    int b  = blockIdx.y;
    const float* Qb = g_Q + ((size_t)b * T_ + Q0) * HD;
    const float* Kb = g_K + (size_t)b * TKP * HD;
    const float* Vb = g_V + (size_t)b * HD * TKP;     // transposed layout

    uint32_t sQ  = (uint32_t)__cvta_generic_to_shared(Qs);
    uint32_t sKV = (uint32_t)__cvta_generic_to_shared(KVs);
    int sr = tid >> 3, sc = tid & 7;

    // stage Q (pre-roped/scaled/rounded/interleaved)
#pragma unroll
    for (int it = 0; it < 2; it++) {
        int r = sr + it * 32;
        cpa16(sQ + (uint32_t)((r * QST + sc * 4) * 4),      Qb + (size_t)r * HD + sc * 4);
        cpa16(sQ + (uint32_t)((r * QST + 32 + sc * 4) * 4), Qb + (size_t)r * HD + 32 + sc * 4);
        cpa16(sQ + (uint32_t)((r * QST + 64 + sc * 4) * 4), Qb + (size_t)r * HD + 64 + sc * 4);
        cpa16(sQ + (uint32_t)((r * QST + 96 + sc * 4) * 4), Qb + (size_t)r * HD + 96 + sc * 4);
    }
    asm volatile("cp.async.commit_group;");

    int r0 = rg * 16 + gid, r1 = r0 + 8;
    int kmax0 = (Q0 + r0) >> 2, kmax1 = (Q0 + r1) >> 2;
    int bt = Q0 >> 8;
    int n0 = half * 32;
    int cc = half * 64;

    float m0r = -1e30f, m1r = -1e30f;
    float sp0 = 0.f, sp1 = 0.f, sx0 = 0.f, sx1 = 0.f;
    float Om[8][4], Ox[8][4];
#pragma unroll
    for (int nf = 0; nf < 8; nf++)
#pragma unroll
        for (int j = 0; j < 4; j++) { Om[nf][j] = 0.f; Ox[nf][j] = 0.f; }

    for (int kt = 0; kt < 16; kt++) {
        __syncthreads();                                    // (A)
        // stage K tile [key][interleaved d]
#pragma unroll
        for (int it = 0; it < 2; it++) {
            int r = sr + it * 32;
            const float* src = Kb + (size_t)(kt * 64 + r) * HD;
            cpa16(sKV + (uint32_t)((r * KST + sc * 4) * 4),      src + sc * 4);
            cpa16(sKV + (uint32_t)((r * KST + 32 + sc * 4) * 4), src + 32 + sc * 4);
            cpa16(sKV + (uint32_t)((r * KST + 64 + sc * 4) * 4), src + 64 + sc * 4);
            cpa16(sKV + (uint32_t)((r * KST + 96 + sc * 4) * 4), src + 96 + sc * 4);
        }
        asm volatile("cp.async.commit_group;");
        asm volatile("cp.async.wait_group 0;");
        __syncthreads();                                    // (B)

        // S = Q K^T — LDS.64 frags
        float c[4][4];
#pragma unroll
        for (int nf = 0; nf < 4; nf++)
#pragma unroll
            for (int j = 0; j < 4; j++) c[nf][j] = 0.f;
#pragma unroll
        for (int ks = 0; ks < 16; ks++) {
            int k0 = ks * 8;
            float2 qa0 = *(const float2*)(Qs + r0 * QST + k0 + 2 * tig);
            float2 qa1 = *(const float2*)(Qs + r1 * QST + k0 + 2 * tig);
#pragma unroll
            for (int nf = 0; nf < 4; nf++) {
                float2 kb2 = *(const float2*)(KVs + (n0 + nf * 8 + gid) * KST + k0 + 2 * tig);
                mma8(c[nf], qa0.x, qa1.x, qa0.y, qa1.y, kb2.x, kb2.y);
            }
        }
        float t0 = -1e30f, t1 = -1e30f;
#pragma unroll
        for (int nf = 0; nf < 4; nf++) {
            t0 = fmaxf(t0, fmaxf(c[nf][0], c[nf][1]));
            t1 = fmaxf(t1, fmaxf(c[nf][2], c[nf][3]));
        }
        t0 = fmaxf(t0, __shfl_xor_sync(0xffffffffu, t0, 1));
        t0 = fmaxf(t0, __shfl_xor_sync(0xffffffffu, t0, 2));
        t1 = fmaxf(t1, __shfl_xor_sync(0xffffffffu, t1, 1));
        t1 = fmaxf(t1, __shfl_xor_sync(0xffffffffu, t1, 2));
        if (tig == 0) { wmx[half * 64 + r0] = t0; wmx[half * 64 + r1] = t1; }
        __syncthreads();                                    // (C)

        // stage V tile [d][key-interleaved 64] — overlaps softmax math
#pragma unroll
        for (int it = 0; it < 8; it++) {
            int f = it * 256 + tid;         // 2048 granules: d = f>>4, gr = f&15
            int d = f >> 4, gr = f & 15;
            cpa16(sKV + (uint32_t)((d * VST + gr * 4) * 4),
                  Vb + (size_t)d * TKP + kt * 64 + gr * 4);
        }
        asm volatile("cp.async.commit_group;");

        float mn0 = fmaxf(m0r, fmaxf(wmx[r0], wmx[64 + r0]));
        float mn1 = fmaxf(m1r, fmaxf(wmx[r1], wmx[64 + r1]));
        float sc0 = __expf(m0r - mn0);
        float sc1 = __expf(m1r - mn1);
        m0r = mn0; m1r = mn1;
        sp0 *= sc0; sx0 *= sc0; sp1 *= sc1; sx1 *= sc1;
#pragma unroll
        for (int nf = 0; nf < 8; nf++) {
            Om[nf][0] *= sc0; Om[nf][1] *= sc0; Om[nf][2] *= sc1; Om[nf][3] *= sc1;
            Ox[nf][0] *= sc0; Ox[nf][1] *= sc0; Ox[nf][2] *= sc1; Ox[nf][3] *= sc1;
        }
        float lp0 = 0.f, lx0 = 0.f, lp1 = 0.f, lx1 = 0.f;
#pragma unroll
        for (int nf = 0; nf < 4; nf++) {
            int kl = n0 + nf * 8 + 2 * tig;
            int kg = kt * 64 + kl;
            float p0 = f2tf(__expf(c[nf][0] - mn0));
            float p1 = f2tf(__expf(c[nf][1] - mn0));
            float p2 = f2tf(__expf(c[nf][2] - mn1));
            float p3 = f2tf(__expf(c[nf][3] - mn1));
            *(float2*)(Ps + r0 * PST + kl) = make_float2(p0, p1);
            *(float2*)(Ps + r1 * PST + kl) = make_float2(p2, p3);
            if (kg     <= kmax0) lp0 += p0; else lx0 += p0;
            if (kg + 1 <= kmax0) lp0 += p1; else lx0 += p1;
            if (kg     <= kmax1) lp1 += p2; else lx1 += p2;
            if (kg + 1 <= kmax1) lp1 += p3; else lx1 += p3;
        }
        lp0 += __shfl_xor_sync(0xffffffffu, lp0, 1); lp0 += __shfl_xor_sync(0xffffffffu, lp0, 2);
        lx0 += __shfl_xor_sync(0xffffffffu, lx0, 1); lx0 += __shfl_xor_sync(0xffffffffu, lx0, 2);
        lp1 += __shfl_xor_sync(0xffffffffu, lp1, 1); lp1 += __shfl_xor_sync(0xffffffffu, lp1, 2);
        lx1 += __shfl_xor_sync(0xffffffffu, lx1, 1); lx1 += __shfl_xor_sync(0xffffffffu, lx1, 2);
        if (tig == 0) {
            wsp[half * 64 + r0] = lp0; wsp[half * 64 + r1] = lp1;
            wsx[half * 64 + r0] = lx0; wsx[half * 64 + r1] = lx1;
        }
        asm volatile("cp.async.wait_group 0;");
        __syncthreads();                                    // (D)

        sp0 += wsp[r0] + wsp[64 + r0];
        sp1 += wsp[r1] + wsp[64 + r1];
        sx0 += wsx[r0] + wsx[64 + r0];
        sx1 += wsx[r1] + wsx[64 + r1];

        // PV: B-frag = one LDS.64 from transposed-interleaved V
        if (kt < bt) {
#pragma unroll
            for (int ks = 0; ks < 8; ks++) {
                int k0 = ks * 8;
                float a0 = Ps[r0 * PST + k0 + tig];
                float a1 = Ps[r1 * PST + k0 + tig];
                float a2 = Ps[r0 * PST + k0 + tig + 4];
                float a3 = Ps[r1 * PST + k0 + tig + 4];
#pragma unroll
                for (int nf = 0; nf < 8; nf++) {
                    float2 bv = *(const float2*)(KVs + (cc + nf * 8 + gid) * VST + k0 + 2 * tig);
                    mma8(Om[nf], a0, a1, a2, a3, bv.x, bv.y);
                }
            }
        } else if (kt > bt) {
#pragma unroll
            for (int ks = 0; ks < 8; ks++) {
                int k0 = ks * 8;
                float a0 = Ps[r0 * PST + k0 + tig];
                float a1 = Ps[r1 * PST + k0 + tig];
                float a2 = Ps[r0 * PST + k0 + tig + 4];
                float a3 = Ps[r1 * PST + k0 + tig + 4];
#pragma unroll
                for (int nf = 0; nf < 8; nf++) {
                    float2 bv = *(const float2*)(KVs + (cc + nf * 8 + gid) * VST + k0 + 2 * tig);
                    mma8(Ox[nf], a0, a1, a2, a3, bv.x, bv.y);
                }
            }
        } else {
#pragma unroll
            for (int ks = 0; ks < 8; ks++) {
                int k0 = ks * 8;
                int kgA = kt * 64 + k0 + tig;
                int kgB = kgA + 4;
                float a0 = Ps[r0 * PST + k0 + tig];
                float a1 = Ps[r1 * PST + k0 + tig];
                float a2 = Ps[r0 * PST + k0 + tig + 4];
                float a3 = Ps[r1 * PST + k0 + tig + 4];
                float m0_ = (kgA <= kmax0) ? a0 : 0.f;
                float m1_ = (kgA <= kmax1) ? a1 : 0.f;
                float m2_ = (kgB <= kmax0) ? a2 : 0.f;
                float m3_ = (kgB <= kmax1) ? a3 : 0.f;
                float x0_ = a0 - m0_, x1_ = a1 - m1_, x2_ = a2 - m2_, x3_ = a3 - m3_;
#pragma unroll
                for (int nf = 0; nf < 8; nf++) {
                    float2 bv = *(const float2*)(KVs + (cc + nf * 8 + gid) * VST + k0 + 2 * tig);
                    mma8(Om[nf], m0_, m1_, m2_, m3_, bv.x, bv.y);
                    mma8(Ox[nf], x0_, x1_, x2_, x3_, bv.x, bv.y);
                }
            }
        }
    }

    // epilogue: atomic adds into zeroed Out
    float alpha = 1.f / (1.f + __expf(-__ldg(alpha_p)));
    float wp0 = alpha / sp0;
    float wp1 = alpha / sp1;
    float wu0 = (1.f - alpha) / (sp0 + sx0);
    float wu1 = (1.f - alpha) / (sp1 + sx1);

    int qg0 = Q0 + r0, qg1 = Q0 + r1;
    float* O0 = Out + ((size_t)b * T_ + qg0) * HD;
    float* O1 = Out + ((size_t)b * T_ + qg1) * HD;
    float* U0 = Out + ((size_t)b * T_ + (T_ - 1 - qg0)) * HD;
    float* U1 = Out + ((size_t)b * T_ + (T_ - 1 - qg1)) * HD;
#pragma unroll
    for (int nf = 0; nf < 8; nf++) {
        int col = cc + nf * 8 + 2 * tig;
        atomicAdd(O0 + col,     Om[nf][0] * wp0);
        atomicAdd(O0 + col + 1, Om[nf][1] * wp0);
        atomicAdd(O1 + col,     Om[nf][2] * wp1);
        atomicAdd(O1 + col + 1, Om[nf][3] * wp1);
        atomicAdd(U0 + col,     (Om[nf][0] + Ox[nf][0]) * wu0);
        atomicAdd(U0 + col + 1, (Om[nf][1] + Ox[nf][1]) * wu0);
        atomicAdd(U1 + col,     (Om[nf][2] + Ox[nf][2]) * wu1);
        atomicAdd(U1 + col + 1, (Om[nf][3] + Ox[nf][3]) * wu1);
    }
}

// ---------------- launch ----------------
extern "C" void kernel_launch(void* const* d_in, const int* in_sizes, int n_in,
                              void* d_out, int out_size) {
    const float* x  = (const float*)d_in[0];
    const float* Wq = (const float*)d_in[1];
    const float* Wk = (const float*)d_in[2];
    const float* Wv = (const float*)d_in[3];
    const float* fa = (const float*)d_in[9];
    float* out = (float*)d_out;

    const int PROJ_SMEM = (2 * ABUF + 2 * BBUF) * 4;                        // 69632 B
    const int ATTN_SMEM = (64 * QST + 9216 + 64 * PST + 3 * 128) * 4;       // 90624 B
    cudaFuncSetAttribute(proj_k, cudaFuncAttributeMaxDynamicSharedMemorySize, PROJ_SMEM);
    cudaFuncSetAttribute(attn_k, cudaFuncAttributeMaxDynamicSharedMemorySize, ATTN_SMEM);

    theta_k<<<1, 64>>>();
    rope_table_k<<<T_, 64>>>();
    cvtW_k<<<192, 256>>>(Wq, Wk, Wv);
    pool_x_k<<<(B_ * TKP * 128) / 256, 256>>>(x);
    proj_k<<<192, 256, PROJ_SMEM>>>(x);
    ropep_k<<<(B_ * T_ * 8) / 256, 256>>>(0);
    ropep_k<<<(B_ * TKP * 8) / 256, 256>>>(1);
    zero_k<<<(B_ * T_ * HD / 4) / 256, 256>>>(out);
    attn_k<<<dim3(T_ / 64, B_), 256, ATTN_SMEM>>>(fa, out);
}